// round 5
// baseline (speedup 1.0000x reference)
#include <cuda_runtime.h>
#include <math.h>

#define NN 512
#define SS 64
#define CC 1024
#define BB 10
#define SB 8                        // s-positions per streaming CTA
#define PI_ELEMS (NN * SS * CC)

__device__ unsigned char g_counts[NN * CC];   // row histograms, u8 (<=63)
__device__ float         g_lse[NN * SS];      // per-(n,s) log-partition

// ---------------------------------------------------------------------------
// Kernel A: per-row hist + Z + all 64 lse + v zeros. 512 CTAs x 256 threads.
// ---------------------------------------------------------------------------
__global__ __launch_bounds__(256) void row_stats_kernel(
    const int* __restrict__ ban_ids,
    const int* __restrict__ item_ids,
    float* __restrict__ out)
{
    __shared__ int   s_hist[CC];
    __shared__ int   s_ids[SS];
    __shared__ int   s_ban[SS * BB];
    __shared__ int   s_last;
    __shared__ float s_red[8];
    __shared__ float s_Z;

    const int n    = blockIdx.x;
    const int tid  = threadIdx.x;
    const int lane = tid & 31;
    const int wrp  = tid >> 5;

    #pragma unroll
    for (int i = tid; i < CC; i += 256) s_hist[i] = 0;
    if (tid < SS) s_ids[tid] = item_ids[n * SS + tid];
    #pragma unroll
    for (int i = tid; i < SS * BB; i += 256) s_ban[i] = ban_ids[n * SS * BB + i];
    if (tid == 0) s_last = -1;
    if (tid < SS) out[PI_ELEMS + n * SS + tid] = 0.0f;     // v tail zeros
    __syncthreads();

    if (tid < SS && s_ids[tid] != 0) atomicMax(&s_last, tid);   // PAD == 0
    __syncthreads();

    if (tid < SS && s_ids[tid] != 0 && tid != s_last)
        atomicAdd(&s_hist[s_ids[tid]], 1);
    __syncthreads();

    // pack 4 u8 counts + partial Z  (counts<=63: exp never overflows)
    const int c0 = tid * 4;
    const int h0 = s_hist[c0 + 0], h1 = s_hist[c0 + 1];
    const int h2 = s_hist[c0 + 2], h3 = s_hist[c0 + 3];
    reinterpret_cast<unsigned*>(g_counts)[n * (CC / 4) + tid] =
        (unsigned)h0 | ((unsigned)h1 << 8) | ((unsigned)h2 << 16) | ((unsigned)h3 << 24);

    float z = expf((float)h0) + expf((float)h1) + expf((float)h2) + expf((float)h3);
    #pragma unroll
    for (int off = 16; off; off >>= 1)
        z += __shfl_xor_sync(0xffffffffu, z, off);
    if (lane == 0) s_red[wrp] = z;
    __syncthreads();
    if (tid == 0) {
        float t = 0.0f;
        #pragma unroll
        for (int w = 0; w < 8; ++w) t += s_red[w];
        s_Z = t;
    }
    __syncthreads();

    // per-s log-partition with rank-10 distinct-banned correction
    if (tid < SS) {
        const float Z = s_Z;
        float corr = 0.0f;
        int ids[BB];
        #pragma unroll
        for (int j = 0; j < BB; ++j) {
            const int id = s_ban[tid * BB + j];
            ids[j] = id;
            bool dup = false;
            #pragma unroll
            for (int k = 0; k < BB; ++k) if (k < j) dup |= (ids[k] == id);
            if (!dup) corr += expf((float)s_hist[id]);
        }
        g_lse[n * SS + tid] = logf(fmaxf(Z - corr, 1e-35f));
    }
}

// ---------------------------------------------------------------------------
// Kernel B: lean streamer. 4096 CTAs x 256 threads, SB=8 s-positions each.
// Hot loop = 4 FADD + 1 STG.128 per s (immediate-offset stores, no mask).
// Ban fixups = 80 scattered 4B overwrites after one barrier.
// ---------------------------------------------------------------------------
__global__ __launch_bounds__(256) void stream_kernel(
    const int* __restrict__ ban_ids,
    float* __restrict__ out)
{
    const int blk = blockIdx.x;
    const int n   = blk >> 3;                 // SS/SB == 8 chunks per row
    const int s0  = (blk & 7) * SB;
    const int tid = threadIdx.x;

    // L2-hot loads issued first
    const unsigned cw =
        __ldg(&reinterpret_cast<const unsigned*>(g_counts)[n * (CC / 4) + tid]);
    float l[SB];
    #pragma unroll
    for (int s = 0; s < SB; ++s) l[s] = __ldg(&g_lse[n * SS + s0 + s]);

    int myban = 0;
    if (tid < SB * BB) myban = ban_ids[(n * SS + s0) * BB + tid];

    const float f0 = (float)( cw        & 0xffu);
    const float f1 = (float)((cw >>  8) & 0xffu);
    const float f2 = (float)((cw >> 16) & 0xffu);
    const float f3 = (float)( cw >> 24         );

    float4* __restrict__ out4 =
        reinterpret_cast<float4*>(out) + (n * SS + s0) * (CC / 4) + tid;
    #pragma unroll
    for (int s = 0; s < SB; ++s) {
        const float ls = l[s];
        float4 o;
        o.x = f0 - ls; o.y = f1 - ls; o.z = f2 - ls; o.w = f3 - ls;
        out4[s * (CC / 4)] = o;               // STG.128 [R+imm]
    }
    __syncthreads();                          // base stores before fixups

    if (tid < SB * BB) {
        const int s = tid / BB;
        const float ls = __ldg(&g_lse[n * SS + s0 + s]);
        // duplicate banned ids write identical values -> benign race
        out[(n * SS + s0 + s) * CC + myban] =
            (float)g_counts[n * CC + myban] - ls - 1e9f;
    }
}

extern "C" void kernel_launch(void* const* d_in, const int* in_sizes, int n_in,
                              void* d_out, int out_size) {
    // metadata order: null_w (f32, unused), ban_ids (i32 [N,S,B]), item_ids (i32 [N,S])
    const int* ban_ids  = (const int*)d_in[1];
    const int* item_ids = (const int*)d_in[2];
    float* out = (float*)d_out;

    row_stats_kernel<<<NN, 256>>>(ban_ids, item_ids, out);
    stream_kernel<<<NN * (SS / SB), 256>>>(ban_ids, out);
}